// round 12
// baseline (speedup 1.0000x reference)
#include <cuda_runtime.h>
#include <cuda_bf16.h>

// MorletTransform via per-harmonic Goertzel recurrence (f32x2 packed lanes).
// R12: 128-thread blocks (6.75 blocks/SM) for cross-block phase overlap.
// Thread: oct = tid&7 -> harmonics 8o+1..8o+8 as FOUR f32x2 chains;
// seg = tid>>3 -> 64-sample segment (16 segments).
// Loop: 1 LDS.128 (2 duplicated samples) + 16 FFMA2.
// Workers store UNROTATED y; single-warp trig-free tail (rot = E63*E64^s via
// even/odd phasor chains, E128 = E64^2).

#define TWO_PI_F 6.28318530717958647692f

__device__ __forceinline__ unsigned long long fma2(unsigned long long a,
                                                   unsigned long long b,
                                                   unsigned long long c) {
    unsigned long long d;
    asm("fma.rn.f32x2 %0, %1, %2, %3;" : "=l"(d) : "l"(a), "l"(b), "l"(c));
    return d;
}
__device__ __forceinline__ unsigned long long pk(float lo, float hi) {
    unsigned long long d;
    asm("mov.b64 %0, {%1, %2};" : "=l"(d) : "f"(lo), "f"(hi));
    return d;
}
__device__ __forceinline__ void upk(unsigned long long v, float& lo, float& hi) {
    asm("mov.b64 {%0, %1}, %2;" : "=f"(lo), "=f"(hi) : "l"(v));
}

__global__ void __launch_bounds__(128)
morlet_kernel(const float* __restrict__ audio,
              const float* __restrict__ f0,
              float* __restrict__ out_hd,
              float* __restrict__ out_amp) {
    const int f   = blockIdx.x;
    const int tid = threadIdx.x;

    __shared__ __align__(16) unsigned long long w2[1024];   // (w[n],w[n]); 8KB
    __shared__ __align__(16) float2 sPart[16 * 64];         // [seg][harm] y; 8KB
    __shared__ __align__(8)  float sCth[64];
    __shared__ __align__(8)  float sSth[64];
    __shared__ __align__(16) float2 sE63[64];               // e^{-i*2pi*frac(63 fc)}
    __shared__ __align__(16) float2 sE64[64];               // e^{-i*2pi*frac(64 fc)}

    // normalizer = 1/sqrt(pi*tp), tp = sr/half_bw = 16000
    const float normalizer = rsqrtf(3.14159265358979f * 16000.0f);
    const float inv_tp     = 1.0f / 16000.0f;
    const float inv_sr     = 1.0f / 16000.0f;

    // --- issue GMEM loads up front (independent, in flight together) ---
    float4 a0 = ((const float4*)audio)[(size_t)f * 256 + 2 * tid];
    float4 a1 = ((const float4*)audio)[(size_t)f * 256 + 2 * tid + 1];
    const float f0v = f0[f];

    // --- per-harmonic coefficients (overlap the audio loads).
    //     Recurrence coeff: accurate sincosf (cos error amplified by
    //     1/sin(theta) ~51 at k=1). E63/E64: absolute phases, __sincosf ok. ---
    if (tid < 64) {
        float fc = f0v * (float)(tid + 1) * inv_sr;
        float s, c;
        sincosf(TWO_PI_F * fc, &s, &c);
        sCth[tid] = c;
        sSth[tid] = s;
        float p63 = fc * 63.0f; p63 -= floorf(p63);
        float p64 = fc * 64.0f; p64 -= floorf(p64);
        float s63, c63, s64, c64;
        __sincosf(TWO_PI_F * p63, &s63, &c63);
        __sincosf(TWO_PI_F * p64, &s64, &c64);
        sE63[tid] = make_float2(c63, -s63);
        sE64[tid] = make_float2(c64, -s64);
    }

    // --- windowed frame: samples 8*tid .. 8*tid+7, stored duplicated ---
    {
        int n = tid * 8;
        float v[8] = {a0.x, a0.y, a0.z, a0.w, a1.x, a1.y, a1.z, a1.w};
        #pragma unroll
        for (int i = 0; i < 8; i += 2) {
            float d0 = (float)(n + i - 512);
            float d1 = (float)(n + i + 1 - 512);
            float w0 = v[i]     * (normalizer * __expf(-d0 * d0 * inv_tp));
            float w1 = v[i + 1] * (normalizer * __expf(-d1 * d1 * inv_tp));
            ((ulonglong2*)w2)[tid * 4 + i / 2] = make_ulonglong2(pk(w0, w0), pk(w1, w1));
        }
    }
    __syncthreads();   // barrier #1: w2 + coefficients ready

    const int oct = tid & 7;    // harmonics 8o+1 .. 8o+8
    const int seg = tid >> 3;   // 16 segments of 64 samples

    // four coefficient pairs for the four chains
    float2 cthP = ((const float2*)sCth)[4 * oct];
    float2 sthP = ((const float2*)sSth)[4 * oct];
    float2 cthQ = ((const float2*)sCth)[4 * oct + 1];
    float2 sthQ = ((const float2*)sSth)[4 * oct + 1];
    float2 cthR = ((const float2*)sCth)[4 * oct + 2];
    float2 sthR = ((const float2*)sSth)[4 * oct + 2];
    float2 cthS = ((const float2*)sCth)[4 * oct + 3];
    float2 sthS = ((const float2*)sSth)[4 * oct + 3];
    const unsigned long long C2P  = pk(2.0f * cthP.x, 2.0f * cthP.y);
    const unsigned long long C2Q  = pk(2.0f * cthQ.x, 2.0f * cthQ.y);
    const unsigned long long C2R  = pk(2.0f * cthR.x, 2.0f * cthR.y);
    const unsigned long long C2S  = pk(2.0f * cthS.x, 2.0f * cthS.y);
    const unsigned long long NEG1 = pk(-1.0f, -1.0f);

    // --- Goertzel: four f32x2 chains over this thread's 64-sample segment ---
    const ulonglong2* wq = (const ulonglong2*)(w2 + seg * 64);

    unsigned long long p1 = 0ull, p2 = 0ull;
    unsigned long long q1 = 0ull, q2 = 0ull;
    unsigned long long r1 = 0ull, r2 = 0ull;
    unsigned long long s1 = 0ull, s2 = 0ull;
    #pragma unroll 8
    for (int m = 0; m < 32; ++m) {
        ulonglong2 wv = wq[m];                          // 2 samples, duplicated
        // sample 2m
        unsigned long long tp = fma2(NEG1, p2, wv.x);
        unsigned long long np = fma2(C2P, p1, tp);
        unsigned long long tq = fma2(NEG1, q2, wv.x);
        unsigned long long nq = fma2(C2Q, q1, tq);
        unsigned long long tr = fma2(NEG1, r2, wv.x);
        unsigned long long nr = fma2(C2R, r1, tr);
        unsigned long long ts = fma2(NEG1, s2, wv.x);
        unsigned long long ns = fma2(C2S, s1, ts);
        // sample 2m+1
        unsigned long long tp1 = fma2(NEG1, p1, wv.y);
        p1 = fma2(C2P, np, tp1);  p2 = np;
        unsigned long long tq1 = fma2(NEG1, q1, wv.y);
        q1 = fma2(C2Q, nq, tq1);  q2 = nq;
        unsigned long long tr1 = fma2(NEG1, r1, wv.y);
        r1 = fma2(C2R, nr, tr1);  r2 = nr;
        unsigned long long ts1 = fma2(NEG1, s1, wv.y);
        s1 = fma2(C2S, ns, ts1);  s2 = ns;
    }

    // --- store UNROTATED y = (s1 - cos*s2, sin*s2) per harmonic (no trig) ---
    {
        float x1A, x1B, x2A, x2B;
        upk(p1, x1A, x1B); upk(p2, x2A, x2B);
        sPart[seg * 64 + 8 * oct + 0] = make_float2(fmaf(-cthP.x, x2A, x1A), sthP.x * x2A);
        sPart[seg * 64 + 8 * oct + 1] = make_float2(fmaf(-cthP.y, x2B, x1B), sthP.y * x2B);
        upk(q1, x1A, x1B); upk(q2, x2A, x2B);
        sPart[seg * 64 + 8 * oct + 2] = make_float2(fmaf(-cthQ.x, x2A, x1A), sthQ.x * x2A);
        sPart[seg * 64 + 8 * oct + 3] = make_float2(fmaf(-cthQ.y, x2B, x1B), sthQ.y * x2B);
        upk(r1, x1A, x1B); upk(r2, x2A, x2B);
        sPart[seg * 64 + 8 * oct + 4] = make_float2(fmaf(-cthR.x, x2A, x1A), sthR.x * x2A);
        sPart[seg * 64 + 8 * oct + 5] = make_float2(fmaf(-cthR.y, x2B, x1B), sthR.y * x2B);
        upk(s1, x1A, x1B); upk(s2, x2A, x2B);
        sPart[seg * 64 + 8 * oct + 6] = make_float2(fmaf(-cthS.x, x2A, x1A), sthS.x * x2A);
        sPart[seg * 64 + 8 * oct + 7] = make_float2(fmaf(-cthS.y, x2B, x1B), sthS.y * x2B);
    }
    __syncthreads();   // barrier #2: partials visible

    // --- single-warp finish: lane l owns harmonics h = 2l, 2l+1.
    //     rot(s) = E63 * E64^s; even/odd phasor chains stepped by E128. ---
    if (tid < 32) {
        float4 e63 = *(const float4*)&sE63[2 * tid];
        float4 e64 = *(const float4*)&sE64[2 * tid];
        float e128_0re = fmaf(e64.x, e64.x, -e64.y * e64.y);
        float e128_0im = 2.0f * e64.x * e64.y;
        float e128_1re = fmaf(e64.z, e64.z, -e64.w * e64.w);
        float e128_1im = 2.0f * e64.z * e64.w;
        float ev0re = e63.x, ev0im = e63.y;
        float ev1re = e63.z, ev1im = e63.w;
        float od0re = fmaf(e63.x, e64.x, -e63.y * e64.y);
        float od0im = fmaf(e63.x, e64.y,  e63.y * e64.x);
        float od1re = fmaf(e63.z, e64.z, -e63.w * e64.w);
        float od1im = fmaf(e63.z, e64.w,  e63.w * e64.z);

        float ar0 = 0.0f, ai0 = 0.0f, ar1 = 0.0f, ai1 = 0.0f;
        #pragma unroll
        for (int s = 0; s < 16; s += 2) {
            float4 pq = *(const float4*)&sPart[s * 64 + 2 * tid];
            ar0 = fmaf(pq.x, ev0re, ar0); ar0 = fmaf(-pq.y, ev0im, ar0);
            ai0 = fmaf(pq.x, ev0im, ai0); ai0 = fmaf( pq.y, ev0re, ai0);
            ar1 = fmaf(pq.z, ev1re, ar1); ar1 = fmaf(-pq.w, ev1im, ar1);
            ai1 = fmaf(pq.z, ev1im, ai1); ai1 = fmaf( pq.w, ev1re, ai1);
            float4 pr = *(const float4*)&sPart[(s + 1) * 64 + 2 * tid];
            ar0 = fmaf(pr.x, od0re, ar0); ar0 = fmaf(-pr.y, od0im, ar0);
            ai0 = fmaf(pr.x, od0im, ai0); ai0 = fmaf( pr.y, od0re, ai0);
            ar1 = fmaf(pr.z, od1re, ar1); ar1 = fmaf(-pr.w, od1im, ar1);
            ai1 = fmaf(pr.z, od1im, ai1); ai1 = fmaf( pr.w, od1re, ai1);
            float t;
            t     = fmaf(ev0re, e128_0re, -ev0im * e128_0im);
            ev0im = fmaf(ev0re, e128_0im,  ev0im * e128_0re); ev0re = t;
            t     = fmaf(ev1re, e128_1re, -ev1im * e128_1im);
            ev1im = fmaf(ev1re, e128_1im,  ev1im * e128_1re); ev1re = t;
            t     = fmaf(od0re, e128_0re, -od0im * e128_0im);
            od0im = fmaf(od0re, e128_0im,  od0im * e128_0re); od0re = t;
            t     = fmaf(od1re, e128_1re, -od1im * e128_1im);
            od1im = fmaf(od1re, e128_1im,  od1im * e128_1re); od1re = t;
        }

        float mag0 = sqrtf(ar0 * ar0 + ai0 * ai0);
        float mag1 = sqrtf(ar1 * ar1 + ai1 * ai1);
        float fch0 = f0v * (float)(2 * tid + 1) * inv_sr;
        float fch1 = f0v * (float)(2 * tid + 2) * inv_sr;
        if (fch0 > 0.5f) mag0 = 0.0f;   // Nyquist mask
        if (fch1 > 0.5f) mag1 = 0.0f;

        float s = mag0 + mag1;
        #pragma unroll
        for (int o = 16; o > 0; o >>= 1)
            s += __shfl_xor_sync(0xffffffffu, s, o);   // amp in all lanes

        float inv = 1.0f / s;
        ((float2*)out_hd)[f * 32 + tid] = make_float2(mag0 * inv, mag1 * inv);
        if (tid == 0)
            out_amp[f] = fminf(fmaxf(s * 2.0f, 0.0f), 1.0f);
    }
}

extern "C" void kernel_launch(void* const* d_in, const int* in_sizes, int n_in,
                              void* d_out, int out_size) {
    const float* audio = (const float*)d_in[0];
    const float* f0    = (const float*)d_in[1];
    const int frames   = in_sizes[1];  // 2*250*1 = 500
    float* out         = (float*)d_out;
    morlet_kernel<<<frames, 128>>>(audio, f0, out, out + (size_t)frames * 64);
}